// round 1
// baseline (speedup 1.0000x reference)
#include <cuda_runtime.h>
#include <cuda_bf16.h>
#include <math.h>

// Problem constants
#define Bn 64
#define Tn 256
#define En 1024
#define Hn 16
#define HDn 64
#define Mrows (Bn*Tn)          // 16384
#define QKV_N (3*En)           // 3072

// ---------------- scratch (static device globals; no allocation) ----------------
__device__ float g_h[Mrows*En];        // LN1 out, reused as LN2 out
__device__ float g_w[En*QKV_N];        // packed qkv weights [E, 3*E]
__device__ float g_qkv[(size_t)Mrows*QKV_N];
__device__ float g_attn[Mrows*En];
__device__ float g_x1[Mrows*En];
__device__ float g_ff1[Mrows*En];

// ---------------- LayerNorm ----------------
__device__ __forceinline__ float block_reduce_sum(float v, float* sbuf) {
    #pragma unroll
    for (int o = 16; o > 0; o >>= 1) v += __shfl_xor_sync(0xffffffffu, v, o);
    int w = threadIdx.x >> 5;
    if ((threadIdx.x & 31) == 0) sbuf[w] = v;
    __syncthreads();
    if (threadIdx.x < 8) {
        float t = sbuf[threadIdx.x];
        #pragma unroll
        for (int o = 4; o > 0; o >>= 1) t += __shfl_xor_sync(0xffu, t, o);
        if (threadIdx.x == 0) sbuf[0] = t;
    }
    __syncthreads();
    float r = sbuf[0];
    __syncthreads();
    return r;
}

__global__ __launch_bounds__(256) void ln_kernel(
    const float* __restrict__ x, const float* __restrict__ g,
    const float* __restrict__ b, float* __restrict__ out)
{
    __shared__ float sbuf[8];
    int row = blockIdx.x;
    const float* xr = x + (size_t)row * En;
    int tid = threadIdx.x;
    float4 xv = *(const float4*)(xr + tid * 4);
    float s = xv.x + xv.y + xv.z + xv.w;
    s = block_reduce_sum(s, sbuf);
    float mu = s * (1.0f / En);
    float d0 = xv.x - mu, d1 = xv.y - mu, d2 = xv.z - mu, d3 = xv.w - mu;
    float ss = d0*d0 + d1*d1 + d2*d2 + d3*d3;
    ss = block_reduce_sum(ss, sbuf);
    float rstd = rsqrtf(ss * (1.0f / En) + 1e-5f);
    float4 gv = *(const float4*)(g + tid * 4);
    float4 bv = *(const float4*)(b + tid * 4);
    float4 ov;
    ov.x = d0 * rstd * gv.x + bv.x;
    ov.y = d1 * rstd * gv.y + bv.y;
    ov.z = d2 * rstd * gv.z + bv.z;
    ov.w = d3 * rstd * gv.w + bv.w;
    *(float4*)(out + (size_t)row * En + tid * 4) = ov;
}

// ---------------- pack qkv weights: [H,E,HD] x3 -> [E, 3*E] row-major ----------------
__global__ __launch_bounds__(256) void pack_w_kernel(
    const float* __restrict__ wk, const float* __restrict__ wq,
    const float* __restrict__ wv, float* __restrict__ out)
{
    int i = blockIdx.x * 256 + threadIdx.x;
    if (i >= En * QKV_N) return;
    int e = i / QKV_N, c = i % QKV_N;
    int which = c / En, r = c % En;
    int h = r / HDn, d = r % HDn;
    const float* src = (which == 0) ? wk : (which == 1) ? wq : wv;
    out[i] = src[(size_t)h * (En * HDn) + (size_t)e * HDn + d];
}

// ---------------- SGEMM: C[M,N] = A[M,K] @ B[K,N] (+bias)(+res)(relu) ----------------
#define BM 128
#define BN 128
#define BKt 16
#define TM 8
#define TN 8

__global__ __launch_bounds__(256) void sgemm_kernel(
    const float* __restrict__ A, const float* __restrict__ Bm,
    const float* __restrict__ bias, const float* __restrict__ res,
    float* __restrict__ C, int M, int N, int K, int relu)
{
    __shared__ float As[BKt][BM];
    __shared__ float Bs[BKt][BN];
    int tid = threadIdx.x;
    int tx = tid & 15, ty = tid >> 4;
    int row0 = blockIdx.y * BM, col0 = blockIdx.x * BN;

    const float* Aptr = A + (size_t)row0 * K;
    const float* Bptr = Bm + col0;

    float acc[TM][TN];
    #pragma unroll
    for (int i = 0; i < TM; i++)
        #pragma unroll
        for (int j = 0; j < TN; j++) acc[i][j] = 0.0f;

    for (int k0 = 0; k0 < K; k0 += BKt) {
        // A tile: 128 rows x 16 k -> 512 float4 along k, 2 per thread
        #pragma unroll
        for (int i = 0; i < 2; i++) {
            int f = tid + i * 256;
            int m = f >> 2;
            int kc = (f & 3) * 4;
            float4 v = *(const float4*)(Aptr + (size_t)m * K + k0 + kc);
            As[kc + 0][m] = v.x; As[kc + 1][m] = v.y;
            As[kc + 2][m] = v.z; As[kc + 3][m] = v.w;
        }
        // B tile: 16 k x 128 n -> 512 float4 along n, 2 per thread
        #pragma unroll
        for (int i = 0; i < 2; i++) {
            int f = tid + i * 256;
            int kk = f >> 5;
            int nc = (f & 31) * 4;
            *(float4*)(&Bs[kk][nc]) = *(const float4*)(Bptr + (size_t)(k0 + kk) * N + nc);
        }
        __syncthreads();
        #pragma unroll
        for (int kk = 0; kk < BKt; kk++) {
            float a[TM], bfr[TN];
            float4 a0 = *(const float4*)(&As[kk][ty * TM]);
            float4 a1 = *(const float4*)(&As[kk][ty * TM + 4]);
            float4 b0 = *(const float4*)(&Bs[kk][tx * TN]);
            float4 b1 = *(const float4*)(&Bs[kk][tx * TN + 4]);
            a[0]=a0.x; a[1]=a0.y; a[2]=a0.z; a[3]=a0.w;
            a[4]=a1.x; a[5]=a1.y; a[6]=a1.z; a[7]=a1.w;
            bfr[0]=b0.x; bfr[1]=b0.y; bfr[2]=b0.z; bfr[3]=b0.w;
            bfr[4]=b1.x; bfr[5]=b1.y; bfr[6]=b1.z; bfr[7]=b1.w;
            #pragma unroll
            for (int i = 0; i < TM; i++)
                #pragma unroll
                for (int j = 0; j < TN; j++)
                    acc[i][j] += a[i] * bfr[j];
        }
        __syncthreads();
    }
    // epilogue
    #pragma unroll
    for (int i = 0; i < TM; i++) {
        int r = row0 + ty * TM + i;
        #pragma unroll
        for (int j = 0; j < TN; j++) {
            int c = col0 + tx * TN + j;
            float v = acc[i][j];
            if (bias) v += bias[c];
            if (res)  v += res[(size_t)r * N + c];
            if (relu) v = fmaxf(v, 0.0f);
            C[(size_t)r * N + c] = v;
        }
    }
}

// ---------------- causal attention (scores = K . Q^T per reference) ----------------
// qkv layout: [b*T+t][which*1024 + h*64 + d], which: 0=k,1=q,2=v
__global__ __launch_bounds__(256, 1) void attn_kernel(
    const float* __restrict__ qkv, float* __restrict__ out)
{
    extern __shared__ float sm[];
    float* q_s = sm;               // [T][64]
    float* v_s = sm + Tn * HDn;    // [T][64]
    int bh = blockIdx.x;
    int b = bh / Hn, h = bh % Hn;
    int t = threadIdx.x;
    const float* base = qkv + (size_t)(b * Tn) * QKV_N + h * HDn;

    for (int i = threadIdx.x; i < Tn * HDn; i += 256) {
        int s = i >> 6, d = i & 63;
        q_s[i] = base[(size_t)s * QKV_N + En + d];
        v_s[i] = base[(size_t)s * QKV_N + 2 * En + d];
    }
    float kreg[HDn];
    {
        const float* krow = base + (size_t)t * QKV_N;
        #pragma unroll
        for (int d4 = 0; d4 < HDn; d4 += 4) {
            float4 kv = *(const float4*)(krow + d4);
            kreg[d4+0]=kv.x; kreg[d4+1]=kv.y; kreg[d4+2]=kv.z; kreg[d4+3]=kv.w;
        }
    }
    __syncthreads();

    float m = -INFINITY, l = 0.0f;
    float acc[HDn];
    #pragma unroll
    for (int d = 0; d < HDn; d++) acc[d] = 0.0f;

    const float scale = 0.125f;  // 1/sqrt(64)
    for (int s = 0; s <= t; s++) {
        const float* qp = &q_s[s << 6];
        float sc = 0.0f;
        #pragma unroll
        for (int d = 0; d < HDn; d++) sc += kreg[d] * qp[d];
        sc *= scale;
        float p;
        if (sc <= m) {
            p = __expf(sc - m);
        } else {
            float corr = __expf(m - sc);   // exp(-inf)=0 on first hit
            l *= corr;
            #pragma unroll
            for (int d = 0; d < HDn; d++) acc[d] *= corr;
            m = sc;
            p = 1.0f;
        }
        l += p;
        const float* vp = &v_s[s << 6];
        #pragma unroll
        for (int d = 0; d < HDn; d++) acc[d] += p * vp[d];
    }
    float inv = 1.0f / l;
    float* op = out + (size_t)(b * Tn + t) * En + h * HDn;
    #pragma unroll
    for (int d4 = 0; d4 < HDn; d4 += 4) {
        float4 ov;
        ov.x = acc[d4+0]*inv; ov.y = acc[d4+1]*inv;
        ov.z = acc[d4+2]*inv; ov.w = acc[d4+3]*inv;
        *(float4*)(op + d4) = ov;
    }
}

// ---------------- launch ----------------
extern "C" void kernel_launch(void* const* d_in, const int* in_sizes, int n_in,
                              void* d_out, int out_size)
{
    const float* x      = (const float*)d_in[0];
    const float* ln1_g  = (const float*)d_in[1];
    const float* ln1_b  = (const float*)d_in[2];
    const float* wk     = (const float*)d_in[3];
    const float* wq     = (const float*)d_in[4];
    const float* wv     = (const float*)d_in[5];
    const float* w_proj = (const float*)d_in[6];
    const float* b_proj = (const float*)d_in[7];
    const float* ln2_g  = (const float*)d_in[8];
    const float* ln2_b  = (const float*)d_in[9];
    const float* w1     = (const float*)d_in[10];
    const float* b1     = (const float*)d_in[11];
    const float* w2     = (const float*)d_in[12];
    const float* b2     = (const float*)d_in[13];
    float* out = (float*)d_out;

    void* p;
    float *h_buf, *w_buf, *qkv, *attn, *x1, *ff1;
    cudaGetSymbolAddress(&p, g_h);    h_buf = (float*)p;
    cudaGetSymbolAddress(&p, g_w);    w_buf = (float*)p;
    cudaGetSymbolAddress(&p, g_qkv);  qkv   = (float*)p;
    cudaGetSymbolAddress(&p, g_attn); attn  = (float*)p;
    cudaGetSymbolAddress(&p, g_x1);   x1    = (float*)p;
    cudaGetSymbolAddress(&p, g_ff1);  ff1   = (float*)p;

    // attention needs 128KB dynamic smem
    int attn_smem = Tn * HDn * 2 * (int)sizeof(float);
    cudaFuncSetAttribute(attn_kernel, cudaFuncAttributeMaxDynamicSharedMemorySize, attn_smem);

    // 1) LN1
    ln_kernel<<<Mrows, 256>>>(x, ln1_g, ln1_b, h_buf);
    // 2) pack qkv weights
    pack_w_kernel<<<(En * QKV_N + 255) / 256, 256>>>(wk, wq, wv, w_buf);
    // 3) fused QKV GEMM: [16384,1024] @ [1024,3072]
    sgemm_kernel<<<dim3(QKV_N / BN, Mrows / BM), 256>>>(
        h_buf, w_buf, nullptr, nullptr, qkv, Mrows, QKV_N, En, 0);
    // 4) attention
    attn_kernel<<<Bn * Hn, 256, attn_smem>>>(qkv, attn);
    // 5) proj + bias + residual(x) -> x1
    sgemm_kernel<<<dim3(En / BN, Mrows / BM), 256>>>(
        attn, w_proj, b_proj, x, x1, Mrows, En, En, 0);
    // 6) LN2
    ln_kernel<<<Mrows, 256>>>(x1, ln2_g, ln2_b, h_buf);
    // 7) FFN1 + bias + relu
    sgemm_kernel<<<dim3(En / BN, Mrows / BM), 256>>>(
        h_buf, w1, b1, nullptr, ff1, Mrows, En, En, 1);
    // 8) FFN2 + bias + residual(x1) -> out
    sgemm_kernel<<<dim3(En / BN, Mrows / BM), 256>>>(
        ff1, w2, b2, x1, out, Mrows, En, En, 0);
}

// round 3
// speedup vs baseline: 1.9708x; 1.9708x over previous
#include <cuda_runtime.h>
#include <cuda_bf16.h>
#include <math.h>
#include <stdint.h>

// Problem constants
#define Bn 64
#define Tn 256
#define En 1024
#define Hn 16
#define HDn 64
#define Mrows (Bn*Tn)          // 16384
#define QKV_N (3*En)           // 3072
#define Kdim 1024              // all GEMMs have K=1024

// ---------------- scratch (static device globals; no allocation) ----------------
__device__ __nv_bfloat16 g_hHi[(size_t)Mrows*En];
__device__ __nv_bfloat16 g_hLo[(size_t)Mrows*En];
__device__ float         g_qkv[(size_t)Mrows*QKV_N];
__device__ __nv_bfloat16 g_attnHi[(size_t)Mrows*En];
__device__ __nv_bfloat16 g_attnLo[(size_t)Mrows*En];
__device__ float         g_x1[(size_t)Mrows*En];
__device__ __nv_bfloat16 g_ff1Hi[(size_t)Mrows*En];
__device__ __nv_bfloat16 g_ff1Lo[(size_t)Mrows*En];
// weights, B-operand layout [N,K] K-major
__device__ __nv_bfloat16 g_wqkvHi[(size_t)QKV_N*Kdim];
__device__ __nv_bfloat16 g_wqkvLo[(size_t)QKV_N*Kdim];
__device__ __nv_bfloat16 g_wpHi[(size_t)En*Kdim];
__device__ __nv_bfloat16 g_wpLo[(size_t)En*Kdim];
__device__ __nv_bfloat16 g_w1Hi[(size_t)En*Kdim];
__device__ __nv_bfloat16 g_w1Lo[(size_t)En*Kdim];
__device__ __nv_bfloat16 g_w2Hi[(size_t)En*Kdim];
__device__ __nv_bfloat16 g_w2Lo[(size_t)En*Kdim];

// ---------------- small helpers ----------------
__device__ __forceinline__ void f2hl(float x, __nv_bfloat16& h, __nv_bfloat16& l) {
    h = __float2bfloat16(x);
    l = __float2bfloat16(x - __bfloat162float(h));
}
__device__ __forceinline__ uint32_t smem_u32(const void* p) {
    uint32_t a;
    asm("{ .reg .u64 t; cvta.to.shared.u64 t, %1; cvt.u32.u64 %0, t; }" : "=r"(a) : "l"(p));
    return a;
}

#define CP_ASYNC16(dst, src) \
    asm volatile("cp.async.cg.shared.global [%0], [%1], 16;" :: "r"(dst), "l"(src) : "memory")
#define CP_COMMIT() asm volatile("cp.async.commit_group;" ::: "memory")
#define CP_WAIT1()  asm volatile("cp.async.wait_group 1;" ::: "memory")
#define CP_WAIT0()  asm volatile("cp.async.wait_group 0;" ::: "memory")

#define LDMX4(r, addr) \
    asm volatile("ldmatrix.sync.aligned.m8n8.x4.shared.b16 {%0,%1,%2,%3}, [%4];" \
        : "=r"((r)[0]),"=r"((r)[1]),"=r"((r)[2]),"=r"((r)[3]) : "r"(addr))

#define MMA16816(d, a, b0, b1) \
    asm volatile("mma.sync.aligned.m16n8k16.row.col.f32.bf16.bf16.f32 " \
        "{%0,%1,%2,%3},{%4,%5,%6,%7},{%8,%9},{%0,%1,%2,%3};" \
        : "+f"((d)[0]),"+f"((d)[1]),"+f"((d)[2]),"+f"((d)[3]) \
        : "r"((a)[0]),"r"((a)[1]),"r"((a)[2]),"r"((a)[3]), "r"(b0),"r"(b1))

// ---------------- LayerNorm -> bf16 hi/lo ----------------
__device__ __forceinline__ float block_reduce_sum(float v, float* sbuf) {
    #pragma unroll
    for (int o = 16; o > 0; o >>= 1) v += __shfl_xor_sync(0xffffffffu, v, o);
    int w = threadIdx.x >> 5;
    if ((threadIdx.x & 31) == 0) sbuf[w] = v;
    __syncthreads();
    if (threadIdx.x < 8) {
        float t = sbuf[threadIdx.x];
        #pragma unroll
        for (int o = 4; o > 0; o >>= 1) t += __shfl_xor_sync(0xffu, t, o);
        if (threadIdx.x == 0) sbuf[0] = t;
    }
    __syncthreads();
    float r = sbuf[0];
    __syncthreads();
    return r;
}

__global__ __launch_bounds__(256) void ln_hilo_kernel(
    const float* __restrict__ x, const float* __restrict__ g,
    const float* __restrict__ b, __nv_bfloat16* __restrict__ oh,
    __nv_bfloat16* __restrict__ ol)
{
    __shared__ float sbuf[8];
    int row = blockIdx.x;
    const float* xr = x + (size_t)row * En;
    int tid = threadIdx.x;
    float4 xv = *(const float4*)(xr + tid * 4);
    float s = xv.x + xv.y + xv.z + xv.w;
    s = block_reduce_sum(s, sbuf);
    float mu = s * (1.0f / En);
    float d0 = xv.x - mu, d1 = xv.y - mu, d2 = xv.z - mu, d3 = xv.w - mu;
    float ss = d0*d0 + d1*d1 + d2*d2 + d3*d3;
    ss = block_reduce_sum(ss, sbuf);
    float rstd = rsqrtf(ss * (1.0f / En) + 1e-5f);
    float4 gv = *(const float4*)(g + tid * 4);
    float4 bv = *(const float4*)(b + tid * 4);
    float o0 = d0 * rstd * gv.x + bv.x;
    float o1 = d1 * rstd * gv.y + bv.y;
    float o2 = d2 * rstd * gv.z + bv.z;
    float o3 = d3 * rstd * gv.w + bv.w;
    __nv_bfloat16 h0,l0,h1,l1,h2,l2,h3,l3;
    f2hl(o0,h0,l0); f2hl(o1,h1,l1); f2hl(o2,h2,l2); f2hl(o3,h3,l3);
    size_t base = (size_t)row * En + tid * 4;
    *(__nv_bfloat162*)(oh + base)     = __nv_bfloat162(h0, h1);
    *(__nv_bfloat162*)(oh + base + 2) = __nv_bfloat162(h2, h3);
    *(__nv_bfloat162*)(ol + base)     = __nv_bfloat162(l0, l1);
    *(__nv_bfloat162*)(ol + base + 2) = __nv_bfloat162(l2, l3);
}

// ---------------- weight transpose-convert: W[K,N] -> B[N,K] hi/lo ----------------
__global__ __launch_bounds__(1024) void tconv_kernel(
    const float* __restrict__ W, __nv_bfloat16* __restrict__ Bh,
    __nv_bfloat16* __restrict__ Bl, int K, int N)
{
    __shared__ float tile[32][33];
    int tx = threadIdx.x & 31, ty = threadIdx.x >> 5;
    int k = blockIdx.y * 32 + ty, n = blockIdx.x * 32 + tx;
    tile[ty][tx] = W[(size_t)k * N + n];
    __syncthreads();
    int nn = blockIdx.x * 32 + ty, kk = blockIdx.y * 32 + tx;
    float v = tile[tx][ty];
    __nv_bfloat16 h, l; f2hl(v, h, l);
    size_t idx = (size_t)nn * K + kk;
    Bh[idx] = h; Bl[idx] = l;
}

// qkv pack: wk/wq/wv [H,E,HD] -> B[3072,1024] rows n = which*1024 + h*64 + d, col e
__global__ __launch_bounds__(1024) void pack_qkv_kernel(
    const float* __restrict__ wk, const float* __restrict__ wq,
    const float* __restrict__ wv, __nv_bfloat16* __restrict__ Bh,
    __nv_bfloat16* __restrict__ Bl)
{
    __shared__ float tile[32][33];
    int tx = threadIdx.x & 31, ty = threadIdx.x >> 5;
    int wh = blockIdx.z;             // which*16 + h
    int which = wh >> 4, h = wh & 15;
    const float* src = (which == 0) ? wk : (which == 1) ? wq : wv;
    int e = blockIdx.y * 32 + ty;
    int d = blockIdx.x * 32 + tx;
    tile[ty][tx] = src[(size_t)h * (En * HDn) + (size_t)e * HDn + d];
    __syncthreads();
    int n = which * En + h * HDn + blockIdx.x * 32 + ty;
    int ee = blockIdx.y * 32 + tx;
    float v = tile[tx][ty];
    __nv_bfloat16 hh, ll; f2hl(v, hh, ll);
    size_t idx = (size_t)n * Kdim + ee;
    Bh[idx] = hh; Bl[idx] = ll;
}

// ---------------- HMMA GEMM: C[M,N] = (Ah+Al)[M,1024] @ (Bh+Bl)[N,1024]^T ----------------
// CTA tile 128x128, 8 warps (2x4), warp tile 64x32. K chunks of 32, 2-stage cp.async.
// SMEM tile: 128 rows x 32 bf16, row pitch 80B (conflict-free ldmatrix, no swizzle).
#define TPITCH   80
#define TILE_B   (128*TPITCH)     // 10240
#define STAGE_B  (4*TILE_B)       // 40960: Ahi,Alo,Bhi,Blo
#define NCHUNK   (Kdim/32)        // 32

__global__ __launch_bounds__(256, 1) void mma_gemm_kernel(
    const __nv_bfloat16* __restrict__ Ah, const __nv_bfloat16* __restrict__ Al,
    const __nv_bfloat16* __restrict__ Bh, const __nv_bfloat16* __restrict__ Bl,
    const float* __restrict__ bias, const float* __restrict__ res, int relu,
    float* __restrict__ outF, __nv_bfloat16* __restrict__ outH,
    __nv_bfloat16* __restrict__ outL, int N)
{
    extern __shared__ char smem[];
    uint32_t sb = smem_u32(smem);
    int tid  = threadIdx.x;
    int lane = tid & 31, wid = tid >> 5;
    int wm = wid >> 2, wn = wid & 3;      // warp grid 2x4
    int row0 = blockIdx.y * 128, col0 = blockIdx.x * 128;

    const __nv_bfloat16* srcs[4] = {
        Ah + (size_t)row0 * Kdim, Al + (size_t)row0 * Kdim,
        Bh + (size_t)col0 * Kdim, Bl + (size_t)col0 * Kdim };

    // per-thread gmem/smem offsets for the 2 cp.async chunks per tile
    int id0 = tid, id1 = tid + 256;       // chunk ids (0..511): r = id>>2, g = id&3
    int r0g = id0 >> 2, g0 = id0 & 3;
    int r1g = id1 >> 2, g1 = id1 & 3;
    uint32_t so0 = (uint32_t)(r0g * TPITCH + g0 * 16);
    uint32_t so1 = (uint32_t)(r1g * TPITCH + g1 * 16);
    size_t   go0 = (size_t)r0g * Kdim + g0 * 8;
    size_t   go1 = (size_t)r1g * Kdim + g1 * 8;

    float acc[4][4][4];
    #pragma unroll
    for (int i = 0; i < 4; i++)
        #pragma unroll
        for (int j = 0; j < 4; j++)
            #pragma unroll
            for (int q = 0; q < 4; q++) acc[i][j][q] = 0.0f;

    // ldmatrix per-thread addressing
    int rowsel = lane & 15;
    int ghalf  = lane >> 4;               // 0: k0-7, 1: k8-15
    // A: r = wm*64 + fm*16 + rowsel ; B: r = wn*32 + h*16 + rowsel
    uint32_t aRowOff = (uint32_t)((wm * 64 + rowsel) * TPITCH);
    uint32_t bRowOff = (uint32_t)((wn * 32 + rowsel) * TPITCH);

    #define LOAD_CHUNK(c, buf) do { \
        int k0 = (c) * 32; \
        uint32_t bb = sb + (buf) * STAGE_B; \
        _Pragma("unroll") \
        for (int t = 0; t < 4; t++) { \
            const __nv_bfloat16* s = srcs[t]; \
            uint32_t tb = bb + t * TILE_B; \
            CP_ASYNC16(tb + so0, s + go0 + k0); \
            CP_ASYNC16(tb + so1, s + go1 + k0); \
        } \
        CP_COMMIT(); \
    } while (0)

    LOAD_CHUNK(0, 0);

    for (int c = 0; c < NCHUNK; c++) {
        int buf = c & 1;
        if (c + 1 < NCHUNK) { LOAD_CHUNK(c + 1, (c + 1) & 1); CP_WAIT1(); }
        else                { CP_WAIT0(); }
        __syncthreads();

        uint32_t bb = sb + buf * STAGE_B;
        #pragma unroll
        for (int ks = 0; ks < 2; ks++) {
            uint32_t kOff = (uint32_t)((ks * 2 + ghalf) * 16);
            uint32_t fAh[4][4], fAl[4][4], fBh[2][4], fBl[2][4];
            #pragma unroll
            for (int fm = 0; fm < 4; fm++) {
                uint32_t ra = bb + aRowOff + (uint32_t)(fm * 16 * TPITCH) + kOff;
                LDMX4(fAh[fm], ra + 0 * TILE_B);
                LDMX4(fAl[fm], ra + 1 * TILE_B);
            }
            #pragma unroll
            for (int h = 0; h < 2; h++) {
                uint32_t rb = bb + bRowOff + (uint32_t)(h * 16 * TPITCH) + kOff;
                LDMX4(fBh[h], rb + 2 * TILE_B);
                LDMX4(fBl[h], rb + 3 * TILE_B);
            }
            #pragma unroll
            for (int fm = 0; fm < 4; fm++)
                #pragma unroll
                for (int fn = 0; fn < 4; fn++) {
                    int h = fn >> 1, s = fn & 1;
                    MMA16816(acc[fm][fn], fAh[fm], fBh[h][s], fBh[h][s + 2]);
                    MMA16816(acc[fm][fn], fAh[fm], fBl[h][s], fBl[h][s + 2]);
                    MMA16816(acc[fm][fn], fAl[fm], fBh[h][s], fBh[h][s + 2]);
                }
        }
        __syncthreads();
    }
    #undef LOAD_CHUNK

    // epilogue
    #pragma unroll
    for (int fm = 0; fm < 4; fm++) {
        #pragma unroll
        for (int fn = 0; fn < 4; fn++) {
            int r = row0 + wm * 64 + fm * 16 + (lane >> 2);
            int cc = col0 + wn * 32 + fn * 8 + 2 * (lane & 3);
            #pragma unroll
            for (int half = 0; half < 2; half++) {
                int rr = r + half * 8;
                float v0 = acc[fm][fn][half * 2 + 0];
                float v1 = acc[fm][fn][half * 2 + 1];
                if (bias) {
                    float2 bv = *(const float2*)(bias + cc);
                    v0 += bv.x; v1 += bv.y;
                }
                if (res) {
                    float2 rv = *(const float2*)(res + (size_t)rr * N + cc);
                    v0 += rv.x; v1 += rv.y;
                }
                if (relu) { v0 = fmaxf(v0, 0.f); v1 = fmaxf(v1, 0.f); }
                if (outF) {
                    *(float2*)(outF + (size_t)rr * N + cc) = make_float2(v0, v1);
                } else {
                    __nv_bfloat16 h0,l0,h1,l1;
                    f2hl(v0,h0,l0); f2hl(v1,h1,l1);
                    size_t ob = (size_t)rr * N + cc;
                    *(__nv_bfloat162*)(outH + ob) = __nv_bfloat162(h0, h1);
                    *(__nv_bfloat162*)(outL + ob) = __nv_bfloat162(l0, l1);
                }
            }
        }
    }
}

// ---------------- causal attention (scores = K . Q^T per reference) ----------------
__global__ __launch_bounds__(256, 1) void attn_kernel(
    const float* __restrict__ qkv, __nv_bfloat16* __restrict__ outH,
    __nv_bfloat16* __restrict__ outL)
{
    extern __shared__ float sm[];
    float* q_s = sm;               // [T][64]
    float* v_s = sm + Tn * HDn;    // [T][64]
    int bh = blockIdx.x;
    int b = bh / Hn, h = bh % Hn;
    int t = threadIdx.x;
    const float* base = qkv + (size_t)(b * Tn) * QKV_N + h * HDn;

    for (int i = threadIdx.x; i < Tn * HDn; i += 256) {
        int s = i >> 6, d = i & 63;
        q_s[i] = base[(size_t)s * QKV_N + En + d];
        v_s[i] = base[(size_t)s * QKV_N + 2 * En + d];
    }
    float kreg[HDn];
    {
        const float* krow = base + (size_t)t * QKV_N;
        #pragma unroll
        for (int d4 = 0; d4 < HDn; d4 += 4) {
            float4 kv = *(const float4*)(krow + d4);
            kreg[d4+0]=kv.x; kreg[d4+1]=kv.y; kreg[d4+2]=kv.z; kreg[d4+3]=kv.w;
        }
    }
    __syncthreads();

    float m = -INFINITY, l = 0.0f;
    float acc[HDn];
    #pragma unroll
    for (int d = 0; d < HDn; d++) acc[d] = 0.0f;

    const float scale = 0.125f;  // 1/sqrt(64)
    for (int s = 0; s <= t; s++) {
        const float* qp = &q_s[s << 6];
        float sc = 0.0f;
        #pragma unroll
        for (int d = 0; d < HDn; d++) sc += kreg[d] * qp[d];
        sc *= scale;
        float p;
        if (sc <= m) {
            p = __expf(sc - m);
        } else {
            float corr = __expf(m - sc);
            l *= corr;
            #pragma unroll
            for (int d = 0; d < HDn; d++) acc[d] *= corr;
            m = sc;
            p = 1.0f;
        }
        l += p;
        const float* vp = &v_s[s << 6];
        #pragma unroll
        for (int d = 0; d < HDn; d++) acc[d] += p * vp[d];
    }
    float inv = 1.0f / l;
    size_t ob = (size_t)(b * Tn + t) * En + h * HDn;
    #pragma unroll
    for (int d = 0; d < HDn; d += 2) {
        float o0 = acc[d] * inv, o1 = acc[d+1] * inv;
        __nv_bfloat16 h0,l0,h1,l1;
        f2hl(o0,h0,l0); f2hl(o1,h1,l1);
        *(__nv_bfloat162*)(outH + ob + d) = __nv_bfloat162(h0, h1);
        *(__nv_bfloat162*)(outL + ob + d) = __nv_bfloat162(l0, l1);
    }
}

// ---------------- launch ----------------
extern "C" void kernel_launch(void* const* d_in, const int* in_sizes, int n_in,
                              void* d_out, int out_size)
{
    const float* x      = (const float*)d_in[0];
    const float* ln1_g  = (const float*)d_in[1];
    const float* ln1_b  = (const float*)d_in[2];
    const float* wk     = (const float*)d_in[3];
    const float* wq     = (const float*)d_in[4];
    const float* wv     = (const float*)d_in[5];
    const float* w_proj = (const float*)d_in[6];
    const float* b_proj = (const float*)d_in[7];
    const float* ln2_g  = (const float*)d_in[8];
    const float* ln2_b  = (const float*)d_in[9];
    const float* w1     = (const float*)d_in[10];
    const float* b1     = (const float*)d_in[11];
    const float* w2     = (const float*)d_in[12];
    const float* b2     = (const float*)d_in[13];
    float* out = (float*)d_out;

    void* p;
    __nv_bfloat16 *hHi,*hLo,*attnHi,*attnLo,*ff1Hi,*ff1Lo;
    __nv_bfloat16 *wqkvHi,*wqkvLo,*wpHi,*wpLo,*w1Hi,*w1Lo,*w2Hi,*w2Lo;
    float *qkv,*x1;
    cudaGetSymbolAddress(&p, g_hHi);    hHi    = (__nv_bfloat16*)p;
    cudaGetSymbolAddress(&p, g_hLo);    hLo    = (__nv_bfloat16*)p;
    cudaGetSymbolAddress(&p, g_qkv);    qkv    = (float*)p;
    cudaGetSymbolAddress(&p, g_attnHi); attnHi = (__nv_bfloat16*)p;
    cudaGetSymbolAddress(&p, g_attnLo); attnLo = (__nv_bfloat16*)p;
    cudaGetSymbolAddress(&p, g_x1);     x1     = (float*)p;
    cudaGetSymbolAddress(&p, g_ff1Hi);  ff1Hi  = (__nv_bfloat16*)p;
    cudaGetSymbolAddress(&p, g_ff1Lo);  ff1Lo  = (__nv_bfloat16*)p;
    cudaGetSymbolAddress(&p, g_wqkvHi); wqkvHi = (__nv_bfloat16*)p;
    cudaGetSymbolAddress(&p, g_wqkvLo); wqkvLo = (__nv_bfloat16*)p;
    cudaGetSymbolAddress(&p, g_wpHi);   wpHi   = (__nv_bfloat16*)p;
    cudaGetSymbolAddress(&p, g_wpLo);   wpLo   = (__nv_bfloat16*)p;
    cudaGetSymbolAddress(&p, g_w1Hi);   w1Hi   = (__nv_bfloat16*)p;
    cudaGetSymbolAddress(&p, g_w1Lo);   w1Lo   = (__nv_bfloat16*)p;
    cudaGetSymbolAddress(&p, g_w2Hi);   w2Hi   = (__nv_bfloat16*)p;
    cudaGetSymbolAddress(&p, g_w2Lo);   w2Lo   = (__nv_bfloat16*)p;

    int attn_smem = Tn * HDn * 2 * (int)sizeof(float);   // 128KB
    cudaFuncSetAttribute(attn_kernel, cudaFuncAttributeMaxDynamicSharedMemorySize, attn_smem);
    int gemm_smem = 2 * STAGE_B;                          // 80KB
    cudaFuncSetAttribute(mma_gemm_kernel, cudaFuncAttributeMaxDynamicSharedMemorySize, gemm_smem);

    // 1) LN1 -> hi/lo
    ln_hilo_kernel<<<Mrows, 256>>>(x, ln1_g, ln1_b, hHi, hLo);
    // 2) weight conversions
    pack_qkv_kernel<<<dim3(2, 32, 48), 1024>>>(wk, wq, wv, wqkvHi, wqkvLo);
    tconv_kernel<<<dim3(32, 32), 1024>>>(w_proj, wpHi, wpLo, Kdim, En);
    tconv_kernel<<<dim3(32, 32), 1024>>>(w1, w1Hi, w1Lo, Kdim, En);
    tconv_kernel<<<dim3(32, 32), 1024>>>(w2, w2Hi, w2Lo, Kdim, En);
    // 3) QKV GEMM -> fp32 qkv
    mma_gemm_kernel<<<dim3(QKV_N/128, Mrows/128), 256, gemm_smem>>>(
        hHi, hLo, wqkvHi, wqkvLo, nullptr, nullptr, 0, qkv, nullptr, nullptr, QKV_N);
    // 4) attention -> hi/lo
    attn_kernel<<<Bn * Hn, 256, attn_smem>>>(qkv, attnHi, attnLo);
    // 5) proj + bias + residual(x) -> fp32 x1
    mma_gemm_kernel<<<dim3(En/128, Mrows/128), 256, gemm_smem>>>(
        attnHi, attnLo, wpHi, wpLo, b_proj, x, 0, x1, nullptr, nullptr, En);
    // 6) LN2 -> hi/lo
    ln_hilo_kernel<<<Mrows, 256>>>(x1, ln2_g, ln2_b, hHi, hLo);
    // 7) FFN1 + bias + relu -> hi/lo
    mma_gemm_kernel<<<dim3(En/128, Mrows/128), 256, gemm_smem>>>(
        hHi, hLo, w1Hi, w1Lo, b1, nullptr, 1, nullptr, ff1Hi, ff1Lo, En);
    // 8) FFN2 + bias + residual(x1) -> out
    mma_gemm_kernel<<<dim3(En/128, Mrows/128), 256, gemm_smem>>>(
        ff1Hi, ff1Lo, w2Hi, w2Lo, b2, x1, 0, out, nullptr, nullptr, En);
}

// round 4
// speedup vs baseline: 2.7485x; 1.3946x over previous
#include <cuda_runtime.h>
#include <cuda_fp16.h>
#include <math.h>
#include <stdint.h>

// Problem constants
#define Bn 64
#define Tn 256
#define En 1024
#define Hn 16
#define HDn 64
#define Mrows (Bn*Tn)          // 16384
#define QKV_N (3*En)           // 3072
#define Kdim 1024              // all GEMMs have K=1024

// ---------------- scratch (static device globals; no allocation) ----------------
__device__ __half g_hHi[(size_t)Mrows*En];
__device__ __half g_hLo[(size_t)Mrows*En];
__device__ float  g_qkv[(size_t)Mrows*QKV_N];
__device__ __half g_attnHi[(size_t)Mrows*En];
__device__ __half g_attnLo[(size_t)Mrows*En];
__device__ float  g_x1[(size_t)Mrows*En];
__device__ __half g_ff1Hi[(size_t)Mrows*En];
__device__ __half g_ff1Lo[(size_t)Mrows*En];
// weights fp16, B-operand layout [N,K] K-major
__device__ __half g_wqkv[(size_t)QKV_N*Kdim];
__device__ __half g_wp[(size_t)En*Kdim];
__device__ __half g_w1[(size_t)En*Kdim];
__device__ __half g_w2[(size_t)En*Kdim];

// ---------------- small helpers ----------------
__device__ __forceinline__ void f2hl(float x, __half& h, __half& l) {
    h = __float2half_rn(x);
    l = __float2half_rn(x - __half2float(h));
}
__device__ __forceinline__ uint32_t smem_u32(const void* p) {
    uint32_t a;
    asm("{ .reg .u64 t; cvta.to.shared.u64 t, %1; cvt.u32.u64 %0, t; }" : "=r"(a) : "l"(p));
    return a;
}

#define CP_ASYNC16(dst, src) \
    asm volatile("cp.async.cg.shared.global [%0], [%1], 16;" :: "r"(dst), "l"(src) : "memory")
#define CP_COMMIT() asm volatile("cp.async.commit_group;" ::: "memory")
#define CP_WAIT2()  asm volatile("cp.async.wait_group 2;" ::: "memory")
#define CP_WAIT0()  asm volatile("cp.async.wait_group 0;" ::: "memory")

#define LDMX4(r, addr) \
    asm volatile("ldmatrix.sync.aligned.m8n8.x4.shared.b16 {%0,%1,%2,%3}, [%4];" \
        : "=r"((r)[0]),"=r"((r)[1]),"=r"((r)[2]),"=r"((r)[3]) : "r"(addr))

#define MMA16816(d, a, b0, b1) \
    asm volatile("mma.sync.aligned.m16n8k16.row.col.f32.f16.f16.f32 " \
        "{%0,%1,%2,%3},{%4,%5,%6,%7},{%8,%9},{%0,%1,%2,%3};" \
        : "+f"((d)[0]),"+f"((d)[1]),"+f"((d)[2]),"+f"((d)[3]) \
        : "r"((a)[0]),"r"((a)[1]),"r"((a)[2]),"r"((a)[3]), "r"(b0),"r"(b1))

// ---------------- LayerNorm -> fp16 hi/lo ----------------
__device__ __forceinline__ float block_reduce_sum(float v, float* sbuf) {
    #pragma unroll
    for (int o = 16; o > 0; o >>= 1) v += __shfl_xor_sync(0xffffffffu, v, o);
    int w = threadIdx.x >> 5;
    if ((threadIdx.x & 31) == 0) sbuf[w] = v;
    __syncthreads();
    if (threadIdx.x < 8) {
        float t = sbuf[threadIdx.x];
        #pragma unroll
        for (int o = 4; o > 0; o >>= 1) t += __shfl_xor_sync(0xffu, t, o);
        if (threadIdx.x == 0) sbuf[0] = t;
    }
    __syncthreads();
    float r = sbuf[0];
    __syncthreads();
    return r;
}

__global__ __launch_bounds__(256) void ln_hilo_kernel(
    const float* __restrict__ x, const float* __restrict__ g,
    const float* __restrict__ b, __half* __restrict__ oh,
    __half* __restrict__ ol)
{
    __shared__ float sbuf[8];
    int row = blockIdx.x;
    const float* xr = x + (size_t)row * En;
    int tid = threadIdx.x;
    float4 xv = *(const float4*)(xr + tid * 4);
    float s = xv.x + xv.y + xv.z + xv.w;
    s = block_reduce_sum(s, sbuf);
    float mu = s * (1.0f / En);
    float d0 = xv.x - mu, d1 = xv.y - mu, d2 = xv.z - mu, d3 = xv.w - mu;
    float ss = d0*d0 + d1*d1 + d2*d2 + d3*d3;
    ss = block_reduce_sum(ss, sbuf);
    float rstd = rsqrtf(ss * (1.0f / En) + 1e-5f);
    float4 gv = *(const float4*)(g + tid * 4);
    float4 bv = *(const float4*)(b + tid * 4);
    float o0 = d0 * rstd * gv.x + bv.x;
    float o1 = d1 * rstd * gv.y + bv.y;
    float o2 = d2 * rstd * gv.z + bv.z;
    float o3 = d3 * rstd * gv.w + bv.w;
    __half h0,l0,h1,l1,h2,l2,h3,l3;
    f2hl(o0,h0,l0); f2hl(o1,h1,l1); f2hl(o2,h2,l2); f2hl(o3,h3,l3);
    size_t base = (size_t)row * En + tid * 4;
    *(__half2*)(oh + base)     = __halves2half2(h0, h1);
    *(__half2*)(oh + base + 2) = __halves2half2(h2, h3);
    *(__half2*)(ol + base)     = __halves2half2(l0, l1);
    *(__half2*)(ol + base + 2) = __halves2half2(l2, l3);
}

// ---------------- weight transpose-convert: W[K,N] fp32 -> B[N,K] fp16 ----------------
__global__ __launch_bounds__(1024) void tconv_kernel(
    const float* __restrict__ W, __half* __restrict__ Bh, int K, int N)
{
    __shared__ float tile[32][33];
    int tx = threadIdx.x & 31, ty = threadIdx.x >> 5;
    int k = blockIdx.y * 32 + ty, n = blockIdx.x * 32 + tx;
    tile[ty][tx] = W[(size_t)k * N + n];
    __syncthreads();
    int nn = blockIdx.x * 32 + ty, kk = blockIdx.y * 32 + tx;
    Bh[(size_t)nn * K + kk] = __float2half_rn(tile[tx][ty]);
}

// qkv pack: wk/wq/wv [H,E,HD] -> B[3072,1024] rows n = which*1024 + h*64 + d, col e
__global__ __launch_bounds__(1024) void pack_qkv_kernel(
    const float* __restrict__ wk, const float* __restrict__ wq,
    const float* __restrict__ wv, __half* __restrict__ Bh)
{
    __shared__ float tile[32][33];
    int tx = threadIdx.x & 31, ty = threadIdx.x >> 5;
    int wh = blockIdx.z;             // which*16 + h
    int which = wh >> 4, h = wh & 15;
    const float* src = (which == 0) ? wk : (which == 1) ? wq : wv;
    int e = blockIdx.y * 32 + ty;
    int d = blockIdx.x * 32 + tx;
    tile[ty][tx] = src[(size_t)h * (En * HDn) + (size_t)e * HDn + d];
    __syncthreads();
    int n = which * En + h * HDn + blockIdx.x * 32 + ty;
    int ee = blockIdx.y * 32 + tx;
    Bh[(size_t)n * Kdim + ee] = __float2half_rn(tile[tx][ty]);
}

// ---------------- HMMA GEMM: C[M,N] = (Ah+Al)[M,1024] @ Bh[N,1024]^T ----------------
// CTA tile 128x128, 8 warps (2x4), warp tile 64x32. K chunks of 32, 3-stage cp.async.
// SMEM tile: 128 rows x 32 fp16, row pitch 80B (conflict-free ldmatrix).
#define TPITCH   80
#define TILE_B   (128*TPITCH)     // 10240
#define STAGE_B  (3*TILE_B)       // 30720: Ahi, Alo, Bh
#define NCHUNK   (Kdim/32)        // 32
#define GEMM_SMEM (3*STAGE_B)     // 92160

__global__ __launch_bounds__(256, 2) void mma_gemm_kernel(
    const __half* __restrict__ Ah, const __half* __restrict__ Al,
    const __half* __restrict__ Bw,
    const float* __restrict__ bias, const float* __restrict__ res, int relu,
    float* __restrict__ outF, __half* __restrict__ outH,
    __half* __restrict__ outL, int N)
{
    extern __shared__ char smem[];
    uint32_t sb = smem_u32(smem);
    int tid  = threadIdx.x;
    int lane = tid & 31, wid = tid >> 5;
    int wm = wid >> 2, wn = wid & 3;      // warp grid 2x4
    int row0 = blockIdx.y * 128, col0 = blockIdx.x * 128;

    const __half* srcAh = Ah + (size_t)row0 * Kdim;
    const __half* srcAl = Al + (size_t)row0 * Kdim;
    const __half* srcB  = Bw + (size_t)col0 * Kdim;

    // per-thread gmem/smem offsets: 512 16B-chunks per tile, 2 per thread
    int id0 = tid, id1 = tid + 256;
    int r0g = id0 >> 2, g0 = id0 & 3;
    int r1g = id1 >> 2, g1 = id1 & 3;
    uint32_t so0 = (uint32_t)(r0g * TPITCH + g0 * 16);
    uint32_t so1 = (uint32_t)(r1g * TPITCH + g1 * 16);
    size_t   go0 = (size_t)r0g * Kdim + g0 * 8;
    size_t   go1 = (size_t)r1g * Kdim + g1 * 8;

    float acc[4][4][4];
    #pragma unroll
    for (int i = 0; i < 4; i++)
        #pragma unroll
        for (int j = 0; j < 4; j++)
            #pragma unroll
            for (int q = 0; q < 4; q++) acc[i][j][q] = 0.0f;

    int rowsel = lane & 15;
    int ghalf  = lane >> 4;
    uint32_t aRowOff = (uint32_t)((wm * 64 + rowsel) * TPITCH);
    uint32_t bRowOff = (uint32_t)((wn * 32 + rowsel) * TPITCH);

    #define LOAD_CHUNK(c) do { \
        int k0 = (c) * 32; \
        uint32_t bb = sb + ((c) % 3) * STAGE_B; \
        CP_ASYNC16(bb + 0*TILE_B + so0, srcAh + go0 + k0); \
        CP_ASYNC16(bb + 0*TILE_B + so1, srcAh + go1 + k0); \
        CP_ASYNC16(bb + 1*TILE_B + so0, srcAl + go0 + k0); \
        CP_ASYNC16(bb + 1*TILE_B + so1, srcAl + go1 + k0); \
        CP_ASYNC16(bb + 2*TILE_B + so0, srcB  + go0 + k0); \
        CP_ASYNC16(bb + 2*TILE_B + so1, srcB  + go1 + k0); \
        CP_COMMIT(); \
    } while (0)

    LOAD_CHUNK(0);
    LOAD_CHUNK(1);

    for (int c = 0; c < NCHUNK; c++) {
        if (c + 2 < NCHUNK) { LOAD_CHUNK(c + 2); CP_WAIT2(); }
        else                { CP_WAIT0(); }
        __syncthreads();

        uint32_t bb = sb + (c % 3) * STAGE_B;
        #pragma unroll
        for (int ks = 0; ks < 2; ks++) {
            uint32_t kOff = (uint32_t)((ks * 2 + ghalf) * 16);
            uint32_t fAh[4][4], fAl[4][4], fB[2][4];
            #pragma unroll
            for (int fm = 0; fm < 4; fm++) {
                uint32_t ra = bb + aRowOff + (uint32_t)(fm * 16 * TPITCH) + kOff;
                LDMX4(fAh[fm], ra + 0 * TILE_B);
                LDMX4(fAl[fm], ra + 1 * TILE_B);
            }
            #pragma unroll
            for (int h = 0; h < 2; h++) {
                uint32_t rb = bb + 2 * TILE_B + bRowOff + (uint32_t)(h * 16 * TPITCH) + kOff;
                LDMX4(fB[h], rb);
            }
            #pragma unroll
            for (int fm = 0; fm < 4; fm++)
                #pragma unroll
                for (int fn = 0; fn < 4; fn++) {
                    int h = fn >> 1, s2 = fn & 1;
                    MMA16816(acc[fm][fn], fAh[fm], fB[h][s2], fB[h][s2 + 2]);
                    MMA16816(acc[fm][fn], fAl[fm], fB[h][s2], fB[h][s2 + 2]);
                }
        }
        __syncthreads();
    }
    #undef LOAD_CHUNK

    // epilogue
    #pragma unroll
    for (int fm = 0; fm < 4; fm++) {
        #pragma unroll
        for (int fn = 0; fn < 4; fn++) {
            int r = row0 + wm * 64 + fm * 16 + (lane >> 2);
            int cc = col0 + wn * 32 + fn * 8 + 2 * (lane & 3);
            #pragma unroll
            for (int half = 0; half < 2; half++) {
                int rr = r + half * 8;
                float v0 = acc[fm][fn][half * 2 + 0];
                float v1 = acc[fm][fn][half * 2 + 1];
                if (bias) {
                    float2 bv = *(const float2*)(bias + cc);
                    v0 += bv.x; v1 += bv.y;
                }
                if (res) {
                    float2 rv = *(const float2*)(res + (size_t)rr * N + cc);
                    v0 += rv.x; v1 += rv.y;
                }
                if (relu) { v0 = fmaxf(v0, 0.f); v1 = fmaxf(v1, 0.f); }
                if (outF) {
                    *(float2*)(outF + (size_t)rr * N + cc) = make_float2(v0, v1);
                } else {
                    __half h0,l0,h1,l1;
                    f2hl(v0,h0,l0); f2hl(v1,h1,l1);
                    size_t ob = (size_t)rr * N + cc;
                    *(__half2*)(outH + ob) = __halves2half2(h0, h1);
                    *(__half2*)(outL + ob) = __halves2half2(l0, l1);
                }
            }
        }
    }
}

// ---------------- causal attention (scores = K . Q^T per reference) ----------------
__global__ __launch_bounds__(256, 1) void attn_kernel(
    const float* __restrict__ qkv, __half* __restrict__ outH,
    __half* __restrict__ outL)
{
    extern __shared__ float sm[];
    float* q_s = sm;               // [T][64]
    float* v_s = sm + Tn * HDn;    // [T][64]
    int bh = blockIdx.x;
    int b = bh / Hn, h = bh % Hn;
    int t = threadIdx.x;
    const float* base = qkv + (size_t)(b * Tn) * QKV_N + h * HDn;

    for (int i = threadIdx.x; i < Tn * HDn; i += 256) {
        int s = i >> 6, d = i & 63;
        q_s[i] = base[(size_t)s * QKV_N + En + d];
        v_s[i] = base[(size_t)s * QKV_N + 2 * En + d];
    }
    float kreg[HDn];
    {
        const float* krow = base + (size_t)t * QKV_N;
        #pragma unroll
        for (int d4 = 0; d4 < HDn; d4 += 4) {
            float4 kv = *(const float4*)(krow + d4);
            kreg[d4+0]=kv.x; kreg[d4+1]=kv.y; kreg[d4+2]=kv.z; kreg[d4+3]=kv.w;
        }
    }
    __syncthreads();

    float m = -INFINITY, l = 0.0f;
    float acc[HDn];
    #pragma unroll
    for (int d = 0; d < HDn; d++) acc[d] = 0.0f;

    const float scale = 0.125f;  // 1/sqrt(64)
    for (int s = 0; s <= t; s++) {
        const float4* qp = (const float4*)&q_s[s << 6];
        float s0 = 0.f, s1 = 0.f, s2 = 0.f, s3 = 0.f;
        #pragma unroll
        for (int d4 = 0; d4 < 16; d4++) {
            float4 qv = qp[d4];
            s0 += kreg[d4*4+0] * qv.x;
            s1 += kreg[d4*4+1] * qv.y;
            s2 += kreg[d4*4+2] * qv.z;
            s3 += kreg[d4*4+3] * qv.w;
        }
        float sc = ((s0 + s1) + (s2 + s3)) * scale;
        float p;
        if (sc <= m) {
            p = __expf(sc - m);
        } else {
            float corr = __expf(m - sc);
            l *= corr;
            #pragma unroll
            for (int d = 0; d < HDn; d++) acc[d] *= corr;
            m = sc;
            p = 1.0f;
        }
        l += p;
        const float* vp = &v_s[s << 6];
        #pragma unroll
        for (int d = 0; d < HDn; d++) acc[d] += p * vp[d];
    }
    float inv = 1.0f / l;
    size_t ob = (size_t)(b * Tn + t) * En + h * HDn;
    #pragma unroll
    for (int d = 0; d < HDn; d += 2) {
        float o0 = acc[d] * inv, o1 = acc[d+1] * inv;
        __half h0,l0,h1,l1;
        f2hl(o0,h0,l0); f2hl(o1,h1,l1);
        *(__half2*)(outH + ob + d) = __halves2half2(h0, h1);
        *(__half2*)(outL + ob + d) = __halves2half2(l0, l1);
    }
}

// ---------------- launch ----------------
extern "C" void kernel_launch(void* const* d_in, const int* in_sizes, int n_in,
                              void* d_out, int out_size)
{
    const float* x      = (const float*)d_in[0];
    const float* ln1_g  = (const float*)d_in[1];
    const float* ln1_b  = (const float*)d_in[2];
    const float* wk     = (const float*)d_in[3];
    const float* wq     = (const float*)d_in[4];
    const float* wv     = (const float*)d_in[5];
    const float* w_proj = (const float*)d_in[6];
    const float* b_proj = (const float*)d_in[7];
    const float* ln2_g  = (const float*)d_in[8];
    const float* ln2_b  = (const float*)d_in[9];
    const float* w1     = (const float*)d_in[10];
    const float* b1     = (const float*)d_in[11];
    const float* w2     = (const float*)d_in[12];
    const float* b2     = (const float*)d_in[13];
    float* out = (float*)d_out;

    void* p;
    __half *hHi,*hLo,*attnHi,*attnLo,*ff1Hi,*ff1Lo,*wqkv,*wp,*w1h,*w2h;
    float *qkv,*x1;
    cudaGetSymbolAddress(&p, g_hHi);    hHi    = (__half*)p;
    cudaGetSymbolAddress(&p, g_hLo);    hLo    = (__half*)p;
    cudaGetSymbolAddress(&p, g_qkv);    qkv    = (float*)p;
    cudaGetSymbolAddress(&p, g_attnHi); attnHi = (__half*)p;
    cudaGetSymbolAddress(&p, g_attnLo); attnLo = (__half*)p;
    cudaGetSymbolAddress(&p, g_x1);     x1     = (float*)p;
    cudaGetSymbolAddress(&p, g_ff1Hi);  ff1Hi  = (__half*)p;
    cudaGetSymbolAddress(&p, g_ff1Lo);  ff1Lo  = (__half*)p;
    cudaGetSymbolAddress(&p, g_wqkv);   wqkv   = (__half*)p;
    cudaGetSymbolAddress(&p, g_wp);     wp     = (__half*)p;
    cudaGetSymbolAddress(&p, g_w1);     w1h    = (__half*)p;
    cudaGetSymbolAddress(&p, g_w2);     w2h    = (__half*)p;

    int attn_smem = Tn * HDn * 2 * (int)sizeof(float);   // 128KB
    cudaFuncSetAttribute(attn_kernel, cudaFuncAttributeMaxDynamicSharedMemorySize, attn_smem);
    cudaFuncSetAttribute(mma_gemm_kernel, cudaFuncAttributeMaxDynamicSharedMemorySize, GEMM_SMEM);

    // 1) LN1 -> fp16 hi/lo
    ln_hilo_kernel<<<Mrows, 256>>>(x, ln1_g, ln1_b, hHi, hLo);
    // 2) weight conversions (fp16)
    pack_qkv_kernel<<<dim3(2, 32, 48), 1024>>>(wk, wq, wv, wqkv);
    tconv_kernel<<<dim3(32, 32), 1024>>>(w_proj, wp, Kdim, En);
    tconv_kernel<<<dim3(32, 32), 1024>>>(w1, w1h, Kdim, En);
    tconv_kernel<<<dim3(32, 32), 1024>>>(w2, w2h, Kdim, En);
    // 3) QKV GEMM -> fp32 qkv
    mma_gemm_kernel<<<dim3(QKV_N/128, Mrows/128), 256, GEMM_SMEM>>>(
        hHi, hLo, wqkv, nullptr, nullptr, 0, qkv, nullptr, nullptr, QKV_N);
    // 4) attention -> fp16 hi/lo
    attn_kernel<<<Bn * Hn, 256, attn_smem>>>(qkv, attnHi, attnLo);
    // 5) proj + bias + residual(x) -> fp32 x1
    mma_gemm_kernel<<<dim3(En/128, Mrows/128), 256, GEMM_SMEM>>>(
        attnHi, attnLo, wp, b_proj, x, 0, x1, nullptr, nullptr, En);
    // 6) LN2 -> fp16 hi/lo
    ln_hilo_kernel<<<Mrows, 256>>>(x1, ln2_g, ln2_b, hHi, hLo);
    // 7) FFN1 + bias + relu -> fp16 hi/lo
    mma_gemm_kernel<<<dim3(En/128, Mrows/128), 256, GEMM_SMEM>>>(
        hHi, hLo, w1h, b1, nullptr, 1, nullptr, ff1Hi, ff1Lo, En);
    // 8) FFN2 + bias + residual(x1) -> out
    mma_gemm_kernel<<<dim3(En/128, Mrows/128), 256, GEMM_SMEM>>>(
        ff1Hi, ff1Lo, w2h, b2, x1, 0, out, nullptr, nullptr, En);
}

// round 6
// speedup vs baseline: 3.6007x; 1.3101x over previous
#include <cuda_runtime.h>
#include <cuda_fp16.h>
#include <math.h>
#include <stdint.h>

// Problem constants
#define Bn 64
#define Tn 256
#define En 1024
#define Hn 16
#define HDn 64
#define Mrows (Bn*Tn)          // 16384
#define QKV_N (3*En)           // 3072
#define Kdim 1024              // all GEMMs have K=1024

// ---------------- scratch (static device globals; no allocation) ----------------
__device__ __half g_hHi[(size_t)Mrows*En];
__device__ __half g_hLo[(size_t)Mrows*En];
__device__ __half g_qkvHi[(size_t)Mrows*QKV_N];
__device__ __half g_qkvLo[(size_t)Mrows*QKV_N];
__device__ __half g_attnHi[(size_t)Mrows*En];
__device__ __half g_attnLo[(size_t)Mrows*En];
__device__ float  g_x1[(size_t)Mrows*En];
__device__ __half g_ff1Hi[(size_t)Mrows*En];
__device__ __half g_ff1Lo[(size_t)Mrows*En];
// weights fp16, B-operand layout [N,K] K-major
__device__ __half g_wqkv[(size_t)QKV_N*Kdim];
__device__ __half g_wp[(size_t)En*Kdim];
__device__ __half g_w1[(size_t)En*Kdim];
__device__ __half g_w2[(size_t)En*Kdim];

// ---------------- small helpers ----------------
__device__ __forceinline__ void f2hl(float x, __half& h, __half& l) {
    h = __float2half_rn(x);
    l = __float2half_rn(x - __half2float(h));
}
__device__ __forceinline__ uint32_t smem_u32(const void* p) {
    uint32_t a;
    asm("{ .reg .u64 t; cvta.to.shared.u64 t, %1; cvt.u32.u64 %0, t; }" : "=r"(a) : "l"(p));
    return a;
}
__device__ __forceinline__ uint32_t pack_h2(__half lo, __half hi) {
    __half2 t = __halves2half2(lo, hi);
    return *reinterpret_cast<uint32_t*>(&t);
}

#define CP_ASYNC16(dst, src) \
    asm volatile("cp.async.cg.shared.global [%0], [%1], 16;" :: "r"(dst), "l"(src) : "memory")
#define CP_COMMIT() asm volatile("cp.async.commit_group;" ::: "memory")
#define CP_WAIT1()  asm volatile("cp.async.wait_group 1;" ::: "memory")
#define CP_WAIT0()  asm volatile("cp.async.wait_group 0;" ::: "memory")

#define LDMX4(r, addr) \
    asm volatile("ldmatrix.sync.aligned.m8n8.x4.shared.b16 {%0,%1,%2,%3}, [%4];" \
        : "=r"((r)[0]),"=r"((r)[1]),"=r"((r)[2]),"=r"((r)[3]) : "r"(addr))
#define LDMX4T(r, addr) \
    asm volatile("ldmatrix.sync.aligned.m8n8.x4.trans.shared.b16 {%0,%1,%2,%3}, [%4];" \
        : "=r"((r)[0]),"=r"((r)[1]),"=r"((r)[2]),"=r"((r)[3]) : "r"(addr))

#define MMA16816(d, a, b0, b1) \
    asm volatile("mma.sync.aligned.m16n8k16.row.col.f32.f16.f16.f32 " \
        "{%0,%1,%2,%3},{%4,%5,%6,%7},{%8,%9},{%0,%1,%2,%3};" \
        : "+f"((d)[0]),"+f"((d)[1]),"+f"((d)[2]),"+f"((d)[3]) \
        : "r"((a)[0]),"r"((a)[1]),"r"((a)[2]),"r"((a)[3]), "r"(b0),"r"(b1))

// ---------------- LayerNorm -> fp16 hi/lo ----------------
__device__ __forceinline__ float block_reduce_sum(float v, float* sbuf) {
    #pragma unroll
    for (int o = 16; o > 0; o >>= 1) v += __shfl_xor_sync(0xffffffffu, v, o);
    int w = threadIdx.x >> 5;
    if ((threadIdx.x & 31) == 0) sbuf[w] = v;
    __syncthreads();
    if (threadIdx.x < 8) {
        float t = sbuf[threadIdx.x];
        #pragma unroll
        for (int o = 4; o > 0; o >>= 1) t += __shfl_xor_sync(0xffu, t, o);
        if (threadIdx.x == 0) sbuf[0] = t;
    }
    __syncthreads();
    float r = sbuf[0];
    __syncthreads();
    return r;
}

__global__ __launch_bounds__(256) void ln_hilo_kernel(
    const float* __restrict__ x, const float* __restrict__ g,
    const float* __restrict__ b, __half* __restrict__ oh,
    __half* __restrict__ ol)
{
    __shared__ float sbuf[8];
    int row = blockIdx.x;
    const float* xr = x + (size_t)row * En;
    int tid = threadIdx.x;
    float4 xv = *(const float4*)(xr + tid * 4);
    float s = xv.x + xv.y + xv.z + xv.w;
    s = block_reduce_sum(s, sbuf);
    float mu = s * (1.0f / En);
    float d0 = xv.x - mu, d1 = xv.y - mu, d2 = xv.z - mu, d3 = xv.w - mu;
    float ss = d0*d0 + d1*d1 + d2*d2 + d3*d3;
    ss = block_reduce_sum(ss, sbuf);
    float rstd = rsqrtf(ss * (1.0f / En) + 1e-5f);
    float4 gv = *(const float4*)(g + tid * 4);
    float4 bv = *(const float4*)(b + tid * 4);
    float o0 = d0 * rstd * gv.x + bv.x;
    float o1 = d1 * rstd * gv.y + bv.y;
    float o2 = d2 * rstd * gv.z + bv.z;
    float o3 = d3 * rstd * gv.w + bv.w;
    __half h0,l0,h1,l1,h2,l2,h3,l3;
    f2hl(o0,h0,l0); f2hl(o1,h1,l1); f2hl(o2,h2,l2); f2hl(o3,h3,l3);
    size_t base = (size_t)row * En + tid * 4;
    *(__half2*)(oh + base)     = __halves2half2(h0, h1);
    *(__half2*)(oh + base + 2) = __halves2half2(h2, h3);
    *(__half2*)(ol + base)     = __halves2half2(l0, l1);
    *(__half2*)(ol + base + 2) = __halves2half2(l2, l3);
}

// ---------------- weight transpose-convert: W[K,N] fp32 -> B[N,K] fp16 ----------------
__global__ __launch_bounds__(1024) void tconv_kernel(
    const float* __restrict__ W, __half* __restrict__ Bh, int K, int N)
{
    __shared__ float tile[32][33];
    int tx = threadIdx.x & 31, ty = threadIdx.x >> 5;
    int k = blockIdx.y * 32 + ty, n = blockIdx.x * 32 + tx;
    tile[ty][tx] = W[(size_t)k * N + n];
    __syncthreads();
    int nn = blockIdx.x * 32 + ty, kk = blockIdx.y * 32 + tx;
    Bh[(size_t)nn * K + kk] = __float2half_rn(tile[tx][ty]);
}

// qkv pack: wk/wq/wv [H,E,HD] -> B[3072,1024] rows n = which*1024 + h*64 + d, col e
__global__ __launch_bounds__(1024) void pack_qkv_kernel(
    const float* __restrict__ wk, const float* __restrict__ wq,
    const float* __restrict__ wv, __half* __restrict__ Bh)
{
    __shared__ float tile[32][33];
    int tx = threadIdx.x & 31, ty = threadIdx.x >> 5;
    int wh = blockIdx.z;             // which*16 + h
    int which = wh >> 4, h = wh & 15;
    const float* src = (which == 0) ? wk : (which == 1) ? wq : wv;
    int e = blockIdx.y * 32 + ty;
    int d = blockIdx.x * 32 + tx;
    tile[ty][tx] = src[(size_t)h * (En * HDn) + (size_t)e * HDn + d];
    __syncthreads();
    int n = which * En + h * HDn + blockIdx.x * 32 + ty;
    int ee = blockIdx.y * 32 + tx;
    Bh[(size_t)n * Kdim + ee] = __float2half_rn(tile[tx][ty]);
}

// ---------------- HMMA GEMM: C[M,N] = (Ah+Al)[M,1024] @ Bh[N,1024]^T ----------------
#define TPITCH   80
#define TILE_B   (128*TPITCH)     // 10240
#define STAGE_B  (3*TILE_B)       // 30720: Ahi, Alo, Bh
#define NCHUNK   (Kdim/32)        // 32
#define GEMM_SMEM (3*STAGE_B)     // 92160

__global__ __launch_bounds__(256, 2) void mma_gemm_kernel(
    const __half* __restrict__ Ah, const __half* __restrict__ Al,
    const __half* __restrict__ Bw,
    const float* __restrict__ bias, const float* __restrict__ res, int relu,
    float* __restrict__ outF, __half* __restrict__ outH,
    __half* __restrict__ outL, int N)
{
    extern __shared__ char smem[];
    uint32_t sb = smem_u32(smem);
    int tid  = threadIdx.x;
    int lane = tid & 31, wid = tid >> 5;
    int wm = wid >> 2, wn = wid & 3;      // warp grid 2x4
    int row0 = blockIdx.y * 128, col0 = blockIdx.x * 128;

    const __half* srcAh = Ah + (size_t)row0 * Kdim;
    const __half* srcAl = Al + (size_t)row0 * Kdim;
    const __half* srcB  = Bw + (size_t)col0 * Kdim;

    int id0 = tid, id1 = tid + 256;
    int r0g = id0 >> 2, g0 = id0 & 3;
    int r1g = id1 >> 2, g1 = id1 & 3;
    uint32_t so0 = (uint32_t)(r0g * TPITCH + g0 * 16);
    uint32_t so1 = (uint32_t)(r1g * TPITCH + g1 * 16);
    size_t   go0 = (size_t)r0g * Kdim + g0 * 8;
    size_t   go1 = (size_t)r1g * Kdim + g1 * 8;

    float acc[4][4][4];
    #pragma unroll
    for (int i = 0; i < 4; i++)
        #pragma unroll
        for (int j = 0; j < 4; j++)
            #pragma unroll
            for (int q = 0; q < 4; q++) acc[i][j][q] = 0.0f;

    int rowsel = lane & 15;
    int ghalf  = lane >> 4;
    uint32_t aRowOff = (uint32_t)((wm * 64 + rowsel) * TPITCH);
    uint32_t bRowOff = (uint32_t)((wn * 32 + rowsel) * TPITCH);

    #define LOAD_CHUNK(c) do { \
        int k0 = (c) * 32; \
        uint32_t bb = sb + ((c) % 3) * STAGE_B; \
        CP_ASYNC16(bb + 0*TILE_B + so0, srcAh + go0 + k0); \
        CP_ASYNC16(bb + 0*TILE_B + so1, srcAh + go1 + k0); \
        CP_ASYNC16(bb + 1*TILE_B + so0, srcAl + go0 + k0); \
        CP_ASYNC16(bb + 1*TILE_B + so1, srcAl + go1 + k0); \
        CP_ASYNC16(bb + 2*TILE_B + so0, srcB  + go0 + k0); \
        CP_ASYNC16(bb + 2*TILE_B + so1, srcB  + go1 + k0); \
        CP_COMMIT(); \
    } while (0)

    LOAD_CHUNK(0);
    LOAD_CHUNK(1);

    for (int c = 0; c < NCHUNK; c++) {
        if (c + 1 < NCHUNK) CP_WAIT1(); else CP_WAIT0();
        __syncthreads();
        if (c + 2 < NCHUNK) LOAD_CHUNK(c + 2);

        uint32_t bb = sb + (c % 3) * STAGE_B;
        #pragma unroll
        for (int ks = 0; ks < 2; ks++) {
            uint32_t kOff = (uint32_t)((ks * 2 + ghalf) * 16);
            uint32_t fAh[4][4], fAl[4][4], fB[2][4];
            #pragma unroll
            for (int fm = 0; fm < 4; fm++) {
                uint32_t ra = bb + aRowOff + (uint32_t)(fm * 16 * TPITCH) + kOff;
                LDMX4(fAh[fm], ra + 0 * TILE_B);
                LDMX4(fAl[fm], ra + 1 * TILE_B);
            }
            #pragma unroll
            for (int h = 0; h < 2; h++) {
                uint32_t rb = bb + 2 * TILE_B + bRowOff + (uint32_t)(h * 16 * TPITCH) + kOff;
                LDMX4(fB[h], rb);
            }
            #pragma unroll
            for (int fm = 0; fm < 4; fm++)
                #pragma unroll
                for (int fn = 0; fn < 4; fn++) {
                    int h = fn >> 1, s2 = fn & 1;
                    MMA16816(acc[fm][fn], fAh[fm], fB[h][s2], fB[h][s2 + 2]);
                    MMA16816(acc[fm][fn], fAl[fm], fB[h][s2], fB[h][s2 + 2]);
                }
        }
    }
    #undef LOAD_CHUNK
    __syncthreads();

    // epilogue
    #pragma unroll
    for (int fm = 0; fm < 4; fm++) {
        #pragma unroll
        for (int fn = 0; fn < 4; fn++) {
            int r = row0 + wm * 64 + fm * 16 + (lane >> 2);
            int cc = col0 + wn * 32 + fn * 8 + 2 * (lane & 3);
            #pragma unroll
            for (int hf = 0; hf < 2; hf++) {
                int rr = r + hf * 8;
                float v0 = acc[fm][fn][hf * 2 + 0];
                float v1 = acc[fm][fn][hf * 2 + 1];
                if (bias) {
                    float2 bv = *(const float2*)(bias + cc);
                    v0 += bv.x; v1 += bv.y;
                }
                if (res) {
                    float2 rv = *(const float2*)(res + (size_t)rr * N + cc);
                    v0 += rv.x; v1 += rv.y;
                }
                if (relu) { v0 = fmaxf(v0, 0.f); v1 = fmaxf(v1, 0.f); }
                if (outF) {
                    *(float2*)(outF + (size_t)rr * N + cc) = make_float2(v0, v1);
                } else {
                    __half h0,l0,h1,l1;
                    f2hl(v0,h0,l0); f2hl(v1,h1,l1);
                    size_t ob = (size_t)rr * N + cc;
                    *(__half2*)(outH + ob) = __halves2half2(h0, h1);
                    *(__half2*)(outL + ob) = __halves2half2(l0, l1);
                }
            }
        }
    }
}

// ---------------- MMA flash attention (scores = K . Q^T per reference) ----------------
// One CTA per (b,h). smem: 6 tiles [256 x 64] fp16, pitch 72 halfs (144B):
// Kh, Kl, Qh, Ql, Vh, Vl. 8 warps; warp w owns m16 t-blocks {w, 15-w} (balanced causal).
#define APITCHB 144
#define ATILE   (256*APITCHB)   // 36864
#define ATTN_SMEM (6*ATILE)     // 221184

__global__ __launch_bounds__(256, 1) void attn_mma_kernel(
    const __half* __restrict__ qkvHi, const __half* __restrict__ qkvLo,
    __half* __restrict__ outH, __half* __restrict__ outL)
{
    extern __shared__ char smem[];
    uint32_t sb = smem_u32(smem);
    int bh = blockIdx.x;
    int b = bh >> 4, h = bh & 15;
    int tid = threadIdx.x, lane = tid & 31, wid = tid >> 5;

    const size_t rowBase = (size_t)(b * Tn) * QKV_N;
    {
        const __half* srcs[6] = {
            qkvHi + rowBase + h * 64,        qkvLo + rowBase + h * 64,
            qkvHi + rowBase + 1024 + h * 64, qkvLo + rowBase + 1024 + h * 64,
            qkvHi + rowBase + 2048 + h * 64, qkvLo + rowBase + 2048 + h * 64 };
        #pragma unroll
        for (int tl = 0; tl < 6; tl++) {
            uint32_t tb = sb + tl * ATILE;
            const __half* s = srcs[tl];
            #pragma unroll
            for (int i = 0; i < 8; i++) {
                int idx = i * 256 + tid;
                int r = idx >> 3, g = idx & 7;
                CP_ASYNC16(tb + (uint32_t)(r * APITCHB + g * 16), s + (size_t)r * QKV_N + g * 8);
            }
        }
        CP_COMMIT(); CP_WAIT0();
        __syncthreads();
    }
    uint32_t tKh = sb, tKl = sb + ATILE, tQh = sb + 2*ATILE,
             tQl = sb + 3*ATILE, tVh = sb + 4*ATILE, tVl = sb + 5*ATILE;

    const float scale = 0.125f;
    int rsel = lane & 15, ghalf = lane >> 4;
    int lr = lane >> 2, lq = lane & 3;

    #pragma unroll
    for (int hb = 0; hb < 2; hb++) {
        int tb = (hb == 0) ? wid : 15 - wid;
        // preload K A-frags (hi + lo) for all 4 k16 steps
        uint32_t kAh[4][4], kAl[4][4];
        {
            uint32_t rowoff = (uint32_t)((tb * 16 + rsel) * APITCHB);
            #pragma unroll
            for (int k = 0; k < 4; k++) {
                uint32_t coff = (uint32_t)((k * 16 + ghalf * 8) * 2);
                LDMX4(kAh[k], tKh + rowoff + coff);
                LDMX4(kAl[k], tKl + rowoff + coff);
            }
        }
        float accO[8][4];
        #pragma unroll
        for (int n = 0; n < 8; n++)
            #pragma unroll
            for (int e = 0; e < 4; e++) accO[n][e] = 0.0f;
        float mrow0 = -1e30f, mrow1 = -1e30f, lrow0 = 0.0f, lrow1 = 0.0f;

        for (int sbk = 0; sbk <= tb; sbk++) {
            float S[2][4];
            #pragma unroll
            for (int j = 0; j < 2; j++)
                #pragma unroll
                for (int e = 0; e < 4; e++) S[j][e] = 0.0f;
            uint32_t rowoffS = (uint32_t)((sbk * 16 + rsel) * APITCHB);
            #pragma unroll
            for (int k = 0; k < 4; k++) {
                uint32_t coff = (uint32_t)((k * 16 + ghalf * 8) * 2);
                uint32_t qh[4], ql[4];
                LDMX4(qh, tQh + rowoffS + coff);
                LDMX4(ql, tQl + rowoffS + coff);
                MMA16816(S[0], kAh[k], qh[0], qh[2]);
                MMA16816(S[1], kAh[k], qh[1], qh[3]);
                MMA16816(S[0], kAl[k], qh[0], qh[2]);
                MMA16816(S[1], kAl[k], qh[1], qh[3]);
                MMA16816(S[0], kAh[k], ql[0], ql[2]);
                MMA16816(S[1], kAh[k], ql[1], ql[3]);
            }
            // scale + causal mask (diagonal block only)
            #pragma unroll
            for (int j = 0; j < 2; j++)
                #pragma unroll
                for (int e = 0; e < 4; e++) {
                    float v = S[j][e] * scale;
                    if (sbk == tb) {
                        int row = tb * 16 + lr + ((e >> 1) << 3);
                        int col = sbk * 16 + j * 8 + 2 * lq + (e & 1);
                        if (col > row) v = -1e30f;
                    }
                    S[j][e] = v;
                }
            // row max (16 cols spread over quad)
            float mx0 = fmaxf(fmaxf(S[0][0], S[0][1]), fmaxf(S[1][0], S[1][1]));
            float mx1 = fmaxf(fmaxf(S[0][2], S[0][3]), fmaxf(S[1][2], S[1][3]));
            mx0 = fmaxf(mx0, __shfl_xor_sync(0xffffffffu, mx0, 1));
            mx0 = fmaxf(mx0, __shfl_xor_sync(0xffffffffu, mx0, 2));
            mx1 = fmaxf(mx1, __shfl_xor_sync(0xffffffffu, mx1, 1));
            mx1 = fmaxf(mx1, __shfl_xor_sync(0xffffffffu, mx1, 2));
            float mn0 = fmaxf(mrow0, mx0), mn1 = fmaxf(mrow1, mx1);
            float c0 = __expf(mrow0 - mn0), c1 = __expf(mrow1 - mn1);
            mrow0 = mn0; mrow1 = mn1;
            float p00 = __expf(S[0][0] - mn0), p01 = __expf(S[0][1] - mn0);
            float p10 = __expf(S[1][0] - mn0), p11 = __expf(S[1][1] - mn0);
            float p02 = __expf(S[0][2] - mn1), p03 = __expf(S[0][3] - mn1);
            float p12 = __expf(S[1][2] - mn1), p13 = __expf(S[1][3] - mn1);
            float sum0 = p00 + p01 + p10 + p11;
            float sum1 = p02 + p03 + p12 + p13;
            sum0 += __shfl_xor_sync(0xffffffffu, sum0, 1);
            sum0 += __shfl_xor_sync(0xffffffffu, sum0, 2);
            sum1 += __shfl_xor_sync(0xffffffffu, sum1, 1);
            sum1 += __shfl_xor_sync(0xffffffffu, sum1, 2);
            lrow0 = lrow0 * c0 + sum0;
            lrow1 = lrow1 * c1 + sum1;
            // rescale accO
            #pragma unroll
            for (int n = 0; n < 8; n++) {
                accO[n][0] *= c0; accO[n][1] *= c0;
                accO[n][2] *= c1; accO[n][3] *= c1;
            }
            // P -> A frags (hi + lo)
            __half h00,l00,h01,l01,h02,l02,h03,l03;
            __half h10,l10,h11,l11,h12,l12,h13,l13;
            f2hl(p00,h00,l00); f2hl(p01,h01,l01); f2hl(p02,h02,l02); f2hl(p03,h03,l03);
            f2hl(p10,h10,l10); f2hl(p11,h11,l11); f2hl(p12,h12,l12); f2hl(p13,h13,l13);
            uint32_t pAh[4] = { pack_h2(h00,h01), pack_h2(h02,h03),
                                pack_h2(h10,h11), pack_h2(h12,h13) };
            uint32_t pAl[4] = { pack_h2(l00,l01), pack_h2(l02,l03),
                                pack_h2(l10,l11), pack_h2(l12,l13) };
            // PV
            #pragma unroll
            for (int dp = 0; dp < 4; dp++) {
                uint32_t coff = (uint32_t)((dp * 16 + ghalf * 8) * 2);
                uint32_t vh[4], vl[4];
                LDMX4T(vh, tVh + rowoffS + coff);
                LDMX4T(vl, tVl + rowoffS + coff);
                MMA16816(accO[dp*2],   pAh, vh[0], vh[1]);
                MMA16816(accO[dp*2+1], pAh, vh[2], vh[3]);
                MMA16816(accO[dp*2],   pAh, vl[0], vl[1]);
                MMA16816(accO[dp*2+1], pAh, vl[2], vl[3]);
                MMA16816(accO[dp*2],   pAl, vh[0], vh[1]);
                MMA16816(accO[dp*2+1], pAl, vh[2], vh[3]);
            }
        }
        // epilogue for this t-block
        float inv0 = 1.0f / lrow0, inv1 = 1.0f / lrow1;
        int rowA = b * Tn + tb * 16 + lr;
        int rowB = rowA + 8;
        #pragma unroll
        for (int n = 0; n < 8; n++) {
            int d = h * 64 + n * 8 + 2 * lq;
            float v0 = accO[n][0] * inv0, v1 = accO[n][1] * inv0;
            float v2 = accO[n][2] * inv1, v3 = accO[n][3] * inv1;
            __half h0,l0,h1,l1,h2,l2,h3,l3;
            f2hl(v0,h0,l0); f2hl(v1,h1,l1); f2hl(v2,h2,l2); f2hl(v3,h3,l3);
            *(__half2*)(outH + (size_t)rowA * En + d) = __halves2half2(h0, h1);
            *(__half2*)(outL + (size_t)rowA * En + d) = __halves2half2(l0, l1);
            *(__half2*)(outH + (size_t)rowB * En + d) = __halves2half2(h2, h3);
            *(__half2*)(outL + (size_t)rowB * En + d) = __halves2half2(l2, l3);
        }
    }
}

// ---------------- launch ----------------
extern "C" void kernel_launch(void* const* d_in, const int* in_sizes, int n_in,
                              void* d_out, int out_size)
{
    const float* x      = (const float*)d_in[0];
    const float* ln1_g  = (const float*)d_in[1];
    const float* ln1_b  = (const float*)d_in[2];
    const float* wk     = (const float*)d_in[3];
    const float* wq     = (const float*)d_in[4];
    const float* wv     = (const float*)d_in[5];
    const float* w_proj = (const float*)d_in[6];
    const float* b_proj = (const float*)d_in[7];
    const float* ln2_g  = (const float*)d_in[8];
    const float* ln2_b  = (const float*)d_in[9];
    const float* w1     = (const float*)d_in[10];
    const float* b1     = (const float*)d_in[11];
    const float* w2     = (const float*)d_in[12];
    const float* b2     = (const float*)d_in[13];
    float* out = (float*)d_out;

    void* p;
    __half *hHi,*hLo,*qkvHi,*qkvLo,*attnHi,*attnLo,*ff1Hi,*ff1Lo,*wqkv,*wp,*w1h,*w2h;
    float *x1;
    cudaGetSymbolAddress(&p, g_hHi);    hHi    = (__half*)p;
    cudaGetSymbolAddress(&p, g_hLo);    hLo    = (__half*)p;
    cudaGetSymbolAddress(&p, g_qkvHi);  qkvHi  = (__half*)p;
    cudaGetSymbolAddress(&p, g_qkvLo);  qkvLo  = (__half*)p;
    cudaGetSymbolAddress(&p, g_attnHi); attnHi = (__half*)p;
    cudaGetSymbolAddress(&p, g_attnLo); attnLo = (__half*)p;
    cudaGetSymbolAddress(&p, g_x1);     x1     = (float*)p;
    cudaGetSymbolAddress(&p, g_ff1Hi);  ff1Hi  = (__half*)p;
    cudaGetSymbolAddress(&p, g_ff1Lo);  ff1Lo  = (__half*)p;
    cudaGetSymbolAddress(&p, g_wqkv);   wqkv   = (__half*)p;
    cudaGetSymbolAddress(&p, g_wp);     wp     = (__half*)p;
    cudaGetSymbolAddress(&p, g_w1);     w1h    = (__half*)p;
    cudaGetSymbolAddress(&p, g_w2);     w2h    = (__half*)p;

    cudaFuncSetAttribute(attn_mma_kernel, cudaFuncAttributeMaxDynamicSharedMemorySize, ATTN_SMEM);
    cudaFuncSetAttribute(mma_gemm_kernel, cudaFuncAttributeMaxDynamicSharedMemorySize, GEMM_SMEM);

    // 1) LN1 -> fp16 hi/lo
    ln_hilo_kernel<<<Mrows, 256>>>(x, ln1_g, ln1_b, hHi, hLo);
    // 2) weight conversions (fp16)
    pack_qkv_kernel<<<dim3(2, 32, 48), 1024>>>(wk, wq, wv, wqkv);
    tconv_kernel<<<dim3(32, 32), 1024>>>(w_proj, wp, Kdim, En);
    tconv_kernel<<<dim3(32, 32), 1024>>>(w1, w1h, Kdim, En);
    tconv_kernel<<<dim3(32, 32), 1024>>>(w2, w2h, Kdim, En);
    // 3) QKV GEMM -> fp16 hi/lo qkv
    mma_gemm_kernel<<<dim3(QKV_N/128, Mrows/128), 256, GEMM_SMEM>>>(
        hHi, hLo, wqkv, nullptr, nullptr, 0, nullptr, qkvHi, qkvLo, QKV_N);
    // 4) MMA flash attention -> fp16 hi/lo
    attn_mma_kernel<<<Bn * Hn, 256, ATTN_SMEM>>>(qkvHi, qkvLo, attnHi, attnLo);
    // 5) proj + bias + residual(x) -> fp32 x1
    mma_gemm_kernel<<<dim3(En/128, Mrows/128), 256, GEMM_SMEM>>>(
        attnHi, attnLo, wp, b_proj, x, 0, x1, nullptr, nullptr, En);
    // 6) LN2 -> fp16 hi/lo
    ln_hilo_kernel<<<Mrows, 256>>>(x1, ln2_g, ln2_b, hHi, hLo);
    // 7) FFN1 + bias + relu -> fp16 hi/lo
    mma_gemm_kernel<<<dim3(En/128, Mrows/128), 256, GEMM_SMEM>>>(
        hHi, hLo, w1h, b1, nullptr, 1, nullptr, ff1Hi, ff1Lo, En);
    // 8) FFN2 + bias + residual(x1) -> out
    mma_gemm_kernel<<<dim3(En/128, Mrows/128), 256, GEMM_SMEM>>>(
        ff1Hi, ff1Lo, w2h, b2, x1, 0, out, nullptr, nullptr, En);
}